// round 10
// baseline (speedup 1.0000x reference)
#include <cuda_runtime.h>
#include <cuda_fp16.h>
#include <cstdint>

#define D_MODEL   1024
#define D_HID     4096
#define NBANKS    16
#define TOKENS    4096
#define ROWS_CAP  12288

// ---------------- device scratch (static: allocation-free) ------------------
__device__ int    g_cnt[NBANKS];
__device__ int    g_cursor[NBANKS];
__device__ int    g_offs[NBANKS];
__device__ int    g_tope[TOKENS * 2];
__device__ float  g_topg[TOKENS * 2];
__device__ int    g_rowtok[ROWS_CAP];
__device__ float  g_rowgate[ROWS_CAP];
__device__ int    g_tokrow[TOKENS * 2];              // token -> its 2 CSR rows
__device__ __half g_Xh[(size_t)TOKENS * D_MODEL];    // X fp16 (written by router)
__device__ __half g_Hh[(size_t)ROWS_CAP * D_HID];    // H fp16 [row][k]
__device__ float  g_Y[(size_t)ROWS_CAP * D_MODEL];   // per-row G2 output

// ---------------------------- helpers ---------------------------------------
__device__ __forceinline__ uint32_t smem_u32(const void* p) {
    uint32_t a;
    asm("{ .reg .u64 t; cvta.to.shared.u64 t, %1; cvt.u32.u64 %0, t; }"
        : "=r"(a) : "l"(p));
    return a;
}

__device__ __forceinline__ void cp16(uint32_t dst, const void* src) {
    asm volatile("cp.async.cg.shared.global [%0], [%1], 16;" :: "r"(dst), "l"(src));
}
#define CP_COMMIT() asm volatile("cp.async.commit_group;" ::: "memory")
#define CP_WAIT1()  asm volatile("cp.async.wait_group 1;"  ::: "memory")

__device__ __forceinline__ void mma16(float d[4], const uint32_t a[4],
                                      const uint32_t b[2]) {
    asm volatile(
        "mma.sync.aligned.m16n8k16.row.col.f32.f16.f16.f32 "
        "{%0,%1,%2,%3}, {%4,%5,%6,%7}, {%8,%9}, {%0,%1,%2,%3};"
        : "+f"(d[0]), "+f"(d[1]), "+f"(d[2]), "+f"(d[3])
        : "r"(a[0]), "r"(a[1]), "r"(a[2]), "r"(a[3]), "r"(b[0]), "r"(b[1]));
}

// SMEM geometry.
// A (fp16): 128 rows x 40 halfs (32 data + 8 pad) -> frag word = 20g + c,
//   20g mod 32 = {0,20,8,28,16,4,24,12} distinct -> conflict-free all phases.
// B (fp32): 32 k-rows x 132 floats (128 data + 4 pad) -> frag bank =
//   (8c + g) mod 32 distinct over 32 lanes; k-phase shifts uniform.
#define ROWH_A      40
#define LDB_W       132
#define A_STAGE_B   (128 * ROWH_A * 2)          // 10240 B
#define B_STAGE_B   (32 * LDB_W * 4)            // 16896 B
#define STAGE_B     (A_STAGE_B + B_STAGE_B)     // 27136 B (16B-aligned)
#define NSTAGE      3
#define SMEM_BYTES  (1024 + NSTAGE * STAGE_B)   // 82432 B

// ============================================================================
__global__ void zmeta_kernel() {
    int t = threadIdx.x;
    if (t < NBANKS) { g_cnt[t] = 0; g_cursor[t] = 0; }
}

// Router: one warp per token; also emits X in fp16 as a side product.
__global__ __launch_bounds__(256) void router_kernel(
    const float* __restrict__ X, const float* __restrict__ Wr,
    const float* __restrict__ br) {
    int gw = (blockIdx.x * blockDim.x + threadIdx.x) >> 5;
    if (gw >= TOKENS) return;
    int lane = threadIdx.x & 31;
    const float* xr = X + (size_t)gw * D_MODEL;
    __half* xh = g_Xh + (size_t)gw * D_MODEL;

    float acc[NBANKS];
#pragma unroll
    for (int e = 0; e < NBANKS; e++) acc[e] = 0.f;

    for (int i = 0; i < D_MODEL / 32; i++) {
        int k = i * 32 + lane;
        float xv = xr[k];
        xh[k] = __float2half_rn(xv);
        const float4* w4 = (const float4*)(Wr + (size_t)k * NBANKS);
#pragma unroll
        for (int q = 0; q < 4; q++) {
            float4 w = w4[q];
            acc[q * 4 + 0] += xv * w.x;
            acc[q * 4 + 1] += xv * w.y;
            acc[q * 4 + 2] += xv * w.z;
            acc[q * 4 + 3] += xv * w.w;
        }
    }
#pragma unroll
    for (int e = 0; e < NBANKS; e++) {
#pragma unroll
        for (int o = 16; o >= 1; o >>= 1)
            acc[e] += __shfl_xor_sync(0xFFFFFFFFu, acc[e], o);
    }
    if (lane != 0) return;
#pragma unroll
    for (int e = 0; e < NBANKS; e++) acc[e] += br[e];

    float m = acc[0];
#pragma unroll
    for (int e = 1; e < NBANKS; e++) m = fmaxf(m, acc[e]);
    float ex[NBANKS], den = 0.f;
#pragma unroll
    for (int e = 0; e < NBANKS; e++) { ex[e] = expf(acc[e] - m); den += ex[e]; }

    int i1 = 0, i2 = -1;
    float v1 = ex[0], v2 = -1.f;
#pragma unroll
    for (int e = 1; e < NBANKS; e++) {
        if (ex[e] > v1)      { v2 = v1; i2 = i1; v1 = ex[e]; i1 = e; }
        else if (ex[e] > v2) { v2 = ex[e]; i2 = e; }
    }
    float inv = 1.f / den;
    g_tope[gw * 2 + 0] = i1; g_topg[gw * 2 + 0] = v1 * inv;
    g_tope[gw * 2 + 1] = i2; g_topg[gw * 2 + 1] = v2 * inv;
    atomicAdd(&g_cnt[i1], 1);
    atomicAdd(&g_cnt[i2], 1);
}

// Padded CSR offsets + padding-row init (pad rows -> token 0, gate 0)
__global__ void offsets_kernel() {
    __shared__ int soff[NBANKS], scnt[NBANKS];
    int tid = threadIdx.x;
    if (tid == 0) {
        int o = 0;
        for (int e = 0; e < NBANKS; e++) {
            int c = g_cnt[e];
            soff[e] = o; scnt[e] = c; g_offs[e] = o;
            o += ((c + 127) >> 7) << 7;
        }
    }
    __syncthreads();
    for (int e = 0; e < NBANKS; e++) {
        int c = scnt[e];
        int pend = ((c + 127) >> 7) << 7;
        for (int i = c + tid; i < pend; i += blockDim.x) {
            g_rowtok[soff[e] + i] = 0;
            g_rowgate[soff[e] + i] = 0.f;
        }
    }
}

__global__ void scatter_kernel() {
    int t = blockIdx.x * blockDim.x + threadIdx.x;
    if (t >= TOKENS) return;
#pragma unroll
    for (int j = 0; j < 2; j++) {
        int e = g_tope[t * 2 + j];
        float g = g_topg[t * 2 + j];
        int pos = atomicAdd(&g_cursor[e], 1);
        int r = g_offs[e] + pos;
        g_rowtok[r]  = t;
        g_rowgate[r] = g;
        g_tokrow[t * 2 + j] = r;
    }
}

// ============================================================================
// Grouped GEMM: fp16 mma m16n8k16, fp32 accum; 128x128 tile, BK=32, 3-stage
// cp.async.  A (fp16) from g_Xh / g_Hh; B = ORIGINAL fp32 weights [e][k][n],
// converted to fp16 in-register per fragment (no transpose/convert passes).
//   G1: Hh = fp16(relu(gather(Xh) @ W1 + b1));  KD=1024, ND=4096
//   G2: Y[row] = gate * (Hh @ W2 + b2);         KD=4096, ND=1024
// ============================================================================
template <int KD, int ND, bool IS_G2>
__global__ __launch_bounds__(256, 2) void moe_gemm(
    const __half* __restrict__ Abase, const float* __restrict__ W,
    const float* __restrict__ bias) {
    int e = blockIdx.z, nt = blockIdx.y, mt = blockIdx.x;
    int cnt = g_cnt[e];
    if (mt * 128 >= cnt) return;
    int rowbase = g_offs[e] + mt * 128;

    extern __shared__ float sm[];
    float* sgate = sm;                  // [128] gates (G2 only)
    char*  stage = (char*)(sm + 256);

    int t = threadIdx.x, lane = t & 31, wid = t >> 5;
    int wm = wid & 1, wn = wid >> 1;

    if (IS_G2 && t < 128) sgate[t] = g_rowgate[rowbase + t];

    // ---- producers -----------------------------------------------------
    // A: 2 threads/row, 32 B (16 halfs) each -> 2 cp16
    int arow = t >> 1;
    const __half* pa;
    if (!IS_G2)
        pa = Abase + (size_t)g_rowtok[rowbase + arow] * KD + (t & 1) * 16;
    else
        pa = Abase + (size_t)(rowbase + arow) * KD + (t & 1) * 16;
    uint32_t aoff = (uint32_t)arow * (ROWH_A * 2) + (uint32_t)(t & 1) * 32;

    // B: 8 threads per k-row, 64 B (16 floats) each -> 4 cp16
    int brow = t >> 3;                  // k-row 0..31 within chunk
    const float* pb = W + ((size_t)e * KD + brow) * ND
                        + (size_t)nt * 128 + (t & 7) * 16;
    uint32_t boff = A_STAGE_B + (uint32_t)brow * (LDB_W * 4)
                  + (uint32_t)(t & 7) * 64;

    uint32_t sbst = smem_u32(stage);
    auto do_load = [&](int s) {
        uint32_t ab = sbst + (uint32_t)s * STAGE_B;
        cp16(ab + aoff,      pa);
        cp16(ab + aoff + 16, pa + 8);
        cp16(ab + boff,      pb);
        cp16(ab + boff + 16, pb + 4);
        cp16(ab + boff + 32, pb + 8);
        cp16(ab + boff + 48, pb + 12);
        pa += 32;
        pb += (size_t)32 * ND;
    };

    const int NCH = KD / 32;
    do_load(0); CP_COMMIT();
    do_load(1); CP_COMMIT();

    float acc[4][4][4];
#pragma unroll
    for (int a = 0; a < 4; a++)
#pragma unroll
        for (int b = 0; b < 4; b++)
#pragma unroll
            for (int c = 0; c < 4; c++) acc[a][b][c] = 0.f;

    int s = 0;
#pragma unroll 1
    for (int c = 0; c < NCH; c++) {
        CP_WAIT1();
        __syncthreads();
        const __half* As = (const __half*)(stage + (size_t)s * STAGE_B);
        const float*  Bs = (const float*)((const char*)As + A_STAGE_B);

#pragma unroll
        for (int ks = 0; ks < 2; ks++) {
            uint32_t af[4][4], bf[4][2];
#pragma unroll
            for (int mi = 0; mi < 4; mi++) {
                const __half* ap = As + (wm * 64 + mi * 16 + (lane >> 2)) * ROWH_A
                                      + ks * 16 + (lane & 3) * 2;
                af[mi][0] = *(const uint32_t*)ap;
                af[mi][1] = *(const uint32_t*)(ap + 8 * ROWH_A);
                af[mi][2] = *(const uint32_t*)(ap + 8);
                af[mi][3] = *(const uint32_t*)(ap + 8 * ROWH_A + 8);
            }
#pragma unroll
            for (int ni = 0; ni < 4; ni++) {
                int n  = wn * 32 + ni * 8 + (lane >> 2);
                int kb = ks * 16 + (lane & 3) * 2;
                const float* bp = Bs + (size_t)kb * LDB_W + n;
                __half2 h0 = __floats2half2_rn(bp[0],           bp[LDB_W]);
                __half2 h1 = __floats2half2_rn(bp[8 * LDB_W],   bp[9 * LDB_W]);
                bf[ni][0] = *(const uint32_t*)&h0;
                bf[ni][1] = *(const uint32_t*)&h1;
            }
#pragma unroll
            for (int mi = 0; mi < 4; mi++)
#pragma unroll
                for (int ni = 0; ni < 4; ni++)
                    mma16(acc[mi][ni], af[mi], bf[ni]);
        }
        if (c + 2 < NCH) do_load((c + 2) % NSTAGE);
        CP_COMMIT();
        if (++s == NSTAGE) s = 0;
    }

    // ---------------------------- epilogue -----------------------------------
    const float* bp = bias + (size_t)e * ND + (size_t)nt * 128;
#pragma unroll
    for (int mi = 0; mi < 4; mi++) {
#pragma unroll
        for (int ni = 0; ni < 4; ni++) {
            int row = wm * 64 + mi * 16 + (lane >> 2);
            int col = wn * 32 + ni * 8 + 2 * (lane & 3);
            float2 bv = *(const float2*)(bp + col);
            if (!IS_G2) {
                __half2 h0 = __floats2half2_rn(
                    fmaxf(acc[mi][ni][0] + bv.x, 0.f),
                    fmaxf(acc[mi][ni][1] + bv.y, 0.f));
                __half2 h1 = __floats2half2_rn(
                    fmaxf(acc[mi][ni][2] + bv.x, 0.f),
                    fmaxf(acc[mi][ni][3] + bv.y, 0.f));
                *(__half2*)(g_Hh + (size_t)(rowbase + row) * D_HID +
                            (size_t)nt * 128 + col) = h0;
                *(__half2*)(g_Hh + (size_t)(rowbase + row + 8) * D_HID +
                            (size_t)nt * 128 + col) = h1;
            } else {
                float g0 = sgate[row], g1 = sgate[row + 8];
                float2 o0, o1;
                o0.x = (acc[mi][ni][0] + bv.x) * g0;
                o0.y = (acc[mi][ni][1] + bv.y) * g0;
                o1.x = (acc[mi][ni][2] + bv.x) * g1;
                o1.y = (acc[mi][ni][3] + bv.y) * g1;
                *(float2*)(g_Y + (size_t)(rowbase + row) * D_MODEL +
                           (size_t)nt * 128 + col) = o0;
                *(float2*)(g_Y + (size_t)(rowbase + row + 8) * D_MODEL +
                           (size_t)nt * 128 + col) = o1;
            }
        }
    }
}

// Combine: out[t] = Y[row0(t)] + Y[row1(t)]  (one block per token)
__global__ __launch_bounds__(256) void combine_kernel(float* __restrict__ out) {
    int t = blockIdx.x;
    int r0 = g_tokrow[t * 2 + 0];
    int r1 = g_tokrow[t * 2 + 1];
    int c = threadIdx.x * 4;
    float4 a = *(const float4*)(g_Y + (size_t)r0 * D_MODEL + c);
    float4 b = *(const float4*)(g_Y + (size_t)r1 * D_MODEL + c);
    float4 o;
    o.x = a.x + b.x; o.y = a.y + b.y; o.z = a.z + b.z; o.w = a.w + b.w;
    *(float4*)(out + (size_t)t * D_MODEL + c) = o;
}

// ============================================================================
extern "C" void kernel_launch(void* const* d_in, const int* in_sizes, int n_in,
                              void* d_out, int out_size) {
    const float* X  = (const float*)d_in[0];
    const float* Wr = (const float*)d_in[1];
    const float* br = (const float*)d_in[2];
    const float* W1 = (const float*)d_in[3];
    const float* b1 = (const float*)d_in[4];
    const float* W2 = (const float*)d_in[5];
    const float* b2 = (const float*)d_in[6];
    float* out = (float*)d_out;

    cudaFuncSetAttribute(moe_gemm<D_MODEL, D_HID, false>,
                         cudaFuncAttributeMaxDynamicSharedMemorySize, SMEM_BYTES);
    cudaFuncSetAttribute(moe_gemm<D_HID, D_MODEL, true>,
                         cudaFuncAttributeMaxDynamicSharedMemorySize, SMEM_BYTES);

    __half *xh_dev = nullptr, *hh_dev = nullptr;
    cudaGetSymbolAddress((void**)&xh_dev, g_Xh);
    cudaGetSymbolAddress((void**)&hh_dev, g_Hh);

    zmeta_kernel<<<1, 32>>>();
    router_kernel<<<TOKENS / 8, 256>>>(X, Wr, br);
    offsets_kernel<<<1, 256>>>();
    scatter_kernel<<<TOKENS / 256, 256>>>();

    dim3 g1(32, D_HID / 128, NBANKS);     // mt_max x nt x expert
    moe_gemm<D_MODEL, D_HID, false><<<g1, 256, SMEM_BYTES>>>(xh_dev, W1, b1);
    dim3 g2(32, D_MODEL / 128, NBANKS);
    moe_gemm<D_HID, D_MODEL, true><<<g2, 256, SMEM_BYTES>>>(hh_dev, W2, b2);
    combine_kernel<<<TOKENS, 256>>>(out);
}

// round 16
// speedup vs baseline: 1.2120x; 1.2120x over previous
#include <cuda_runtime.h>
#include <cuda_fp16.h>
#include <cstdint>

#define D_MODEL   1024
#define D_HID     4096
#define NBANKS    16
#define TOKENS    4096
#define ROWS_CAP  12288

// ---------------- device scratch (static: allocation-free) ------------------
__device__ int    g_cnt[NBANKS];
__device__ int    g_cursor[NBANKS];
__device__ int    g_offs[NBANKS];
__device__ int    g_tope[TOKENS * 2];
__device__ float  g_topg[TOKENS * 2];
__device__ int    g_rowtok[ROWS_CAP];
__device__ float  g_rowgate[ROWS_CAP];
__device__ int    g_tokrow[TOKENS * 2];              // token -> its 2 CSR rows
__device__ __half g_Xh[(size_t)TOKENS * D_MODEL];    // X fp16 (router side-product)
__device__ __half g_W1h[(size_t)NBANKS * D_MODEL * D_HID];  // W1 fp16 [e][k][n]
__device__ __half g_W2h[(size_t)NBANKS * D_HID * D_MODEL];  // W2 fp16 [e][k][n]
__device__ __half g_Hh[(size_t)ROWS_CAP * D_HID];    // H fp16 [row][k]
__device__ float  g_Y[(size_t)ROWS_CAP * D_MODEL];   // per-row G2 output

// ---------------------------- helpers ---------------------------------------
__device__ __forceinline__ uint32_t smem_u32(const void* p) {
    uint32_t a;
    asm("{ .reg .u64 t; cvta.to.shared.u64 t, %1; cvt.u32.u64 %0, t; }"
        : "=r"(a) : "l"(p));
    return a;
}

__device__ __forceinline__ void cp16(uint32_t dst, const void* src) {
    asm volatile("cp.async.cg.shared.global [%0], [%1], 16;" :: "r"(dst), "l"(src));
}
#define CP_COMMIT() asm volatile("cp.async.commit_group;" ::: "memory")
#define CP_WAIT2()  asm volatile("cp.async.wait_group 2;"  ::: "memory")

__device__ __forceinline__ void ldsm4(uint32_t r[4], uint32_t addr) {
    asm volatile("ldmatrix.sync.aligned.m8n8.x4.shared.b16 {%0,%1,%2,%3}, [%4];"
        : "=r"(r[0]), "=r"(r[1]), "=r"(r[2]), "=r"(r[3]) : "r"(addr));
}
__device__ __forceinline__ void ldsm4t(uint32_t r[4], uint32_t addr) {
    asm volatile("ldmatrix.sync.aligned.m8n8.x4.trans.shared.b16 {%0,%1,%2,%3}, [%4];"
        : "=r"(r[0]), "=r"(r[1]), "=r"(r[2]), "=r"(r[3]) : "r"(addr));
}

__device__ __forceinline__ void mma16(float d[4], const uint32_t a[4],
                                      uint32_t b0, uint32_t b1) {
    asm volatile(
        "mma.sync.aligned.m16n8k16.row.col.f32.f16.f16.f32 "
        "{%0,%1,%2,%3}, {%4,%5,%6,%7}, {%8,%9}, {%0,%1,%2,%3};"
        : "+f"(d[0]), "+f"(d[1]), "+f"(d[2]), "+f"(d[3])
        : "r"(a[0]), "r"(a[1]), "r"(a[2]), "r"(a[3]), "r"(b0), "r"(b1));
}

// SMEM geometry (fp16 both operands, BK=32).
// A: 128 m-rows x 40 halfs (32 data + 8 pad). LDSM word = 20r + c:
//   20r mod 32 = {0,20,8,28,16,4,24,12}; 16B spans tile all 32 banks. CF.
// B: 32 k-rows x 136 halfs (128 data + 8 pad). LDSM word = 68r + n:
//   per-phase spans (4k + n0)..+3 tile all 32 banks. CF.
#define ROWH_A      40
#define LDN_B       136
#define A_STAGE_B   (128 * ROWH_A * 2)          // 10240 B
#define B_STAGE_B   (32 * LDN_B * 2)            // 8704 B
#define STAGE_B     (A_STAGE_B + B_STAGE_B)     // 18944 B (16B-aligned)
#define NSTAGE      4
#define SMEM_BYTES  (1024 + NSTAGE * STAGE_B)   // 76800 B

// ============================================================================
// Prep: W1,W2 fp32 -> fp16 straight copy (no transpose; ldmatrix.trans handles
// layout in the GEMM). Also zeroes dispatch counters (block 0).
// ============================================================================
__global__ __launch_bounds__(256) void prep_kernel(
    const float* __restrict__ W1, const float* __restrict__ W2) {
    int tid = threadIdx.x;
    if (blockIdx.x == 0 && tid < NBANKS) { g_cnt[tid] = 0; g_cursor[tid] = 0; }
    size_t i = ((size_t)blockIdx.x * 256 + tid) * 8;
    {
        float4 a = *(const float4*)(W1 + i);
        float4 b = *(const float4*)(W1 + i + 4);
        uint4 o; __half2 h;
        h = __floats2half2_rn(a.x, a.y); o.x = *(uint32_t*)&h;
        h = __floats2half2_rn(a.z, a.w); o.y = *(uint32_t*)&h;
        h = __floats2half2_rn(b.x, b.y); o.z = *(uint32_t*)&h;
        h = __floats2half2_rn(b.z, b.w); o.w = *(uint32_t*)&h;
        *(uint4*)(g_W1h + i) = o;
    }
    {
        float4 a = *(const float4*)(W2 + i);
        float4 b = *(const float4*)(W2 + i + 4);
        uint4 o; __half2 h;
        h = __floats2half2_rn(a.x, a.y); o.x = *(uint32_t*)&h;
        h = __floats2half2_rn(a.z, a.w); o.y = *(uint32_t*)&h;
        h = __floats2half2_rn(b.x, b.y); o.z = *(uint32_t*)&h;
        h = __floats2half2_rn(b.z, b.w); o.w = *(uint32_t*)&h;
        *(uint4*)(g_W2h + i) = o;
    }
}

// Router: one warp per token; emits X in fp16 as a side product.
__global__ __launch_bounds__(256) void router_kernel(
    const float* __restrict__ X, const float* __restrict__ Wr,
    const float* __restrict__ br) {
    int gw = (blockIdx.x * blockDim.x + threadIdx.x) >> 5;
    if (gw >= TOKENS) return;
    int lane = threadIdx.x & 31;
    const float* xr = X + (size_t)gw * D_MODEL;
    __half* xh = g_Xh + (size_t)gw * D_MODEL;

    float acc[NBANKS];
#pragma unroll
    for (int e = 0; e < NBANKS; e++) acc[e] = 0.f;

    for (int i = 0; i < D_MODEL / 32; i++) {
        int k = i * 32 + lane;
        float xv = xr[k];
        xh[k] = __float2half_rn(xv);
        const float4* w4 = (const float4*)(Wr + (size_t)k * NBANKS);
#pragma unroll
        for (int q = 0; q < 4; q++) {
            float4 w = w4[q];
            acc[q * 4 + 0] += xv * w.x;
            acc[q * 4 + 1] += xv * w.y;
            acc[q * 4 + 2] += xv * w.z;
            acc[q * 4 + 3] += xv * w.w;
        }
    }
#pragma unroll
    for (int e = 0; e < NBANKS; e++) {
#pragma unroll
        for (int o = 16; o >= 1; o >>= 1)
            acc[e] += __shfl_xor_sync(0xFFFFFFFFu, acc[e], o);
    }
    if (lane != 0) return;
#pragma unroll
    for (int e = 0; e < NBANKS; e++) acc[e] += br[e];

    float m = acc[0];
#pragma unroll
    for (int e = 1; e < NBANKS; e++) m = fmaxf(m, acc[e]);
    float ex[NBANKS], den = 0.f;
#pragma unroll
    for (int e = 0; e < NBANKS; e++) { ex[e] = expf(acc[e] - m); den += ex[e]; }

    int i1 = 0, i2 = -1;
    float v1 = ex[0], v2 = -1.f;
#pragma unroll
    for (int e = 1; e < NBANKS; e++) {
        if (ex[e] > v1)      { v2 = v1; i2 = i1; v1 = ex[e]; i1 = e; }
        else if (ex[e] > v2) { v2 = ex[e]; i2 = e; }
    }
    float inv = 1.f / den;
    g_tope[gw * 2 + 0] = i1; g_topg[gw * 2 + 0] = v1 * inv;
    g_tope[gw * 2 + 1] = i2; g_topg[gw * 2 + 1] = v2 * inv;
    atomicAdd(&g_cnt[i1], 1);
    atomicAdd(&g_cnt[i2], 1);
}

// Dispatch (single block): padded CSR offsets + pad-row init + scatter.
__global__ __launch_bounds__(256) void dispatch_kernel() {
    __shared__ int soff[NBANKS];
    int tid = threadIdx.x;
    if (tid == 0) {
        int o = 0;
        for (int e = 0; e < NBANKS; e++) {
            g_offs[e] = o; soff[e] = o;
            o += ((g_cnt[e] + 127) >> 7) << 7;
        }
    }
    __syncthreads();
    for (int e = 0; e < NBANKS; e++) {
        int c = g_cnt[e];
        int pend = ((c + 127) >> 7) << 7;
        for (int i = c + tid; i < pend; i += 256) {
            g_rowtok[soff[e] + i] = 0;
            g_rowgate[soff[e] + i] = 0.f;
        }
    }
    __syncthreads();
    for (int t = tid; t < TOKENS; t += 256) {
#pragma unroll
        for (int j = 0; j < 2; j++) {
            int e = g_tope[t * 2 + j];
            int pos = atomicAdd(&g_cursor[e], 1);
            int r = soff[e] + pos;
            g_rowtok[r]  = t;
            g_rowgate[r] = g_topg[t * 2 + j];
            g_tokrow[t * 2 + j] = r;
        }
    }
}

// ============================================================================
// Grouped GEMM: fp16 mma m16n8k16 (fp32 acc), 128x128 tile, BK=32, 4-stage
// cp.async.  Operand fragments via ldmatrix (A) / ldmatrix.trans (B, [k][n]).
//   G1: Hh = fp16(relu(gather(Xh) @ W1h + b1));  KD=1024, ND=4096
//   G2: Y[row] = gate * (Hh @ W2h + b2);         KD=4096, ND=1024
// ============================================================================
template <int KD, int ND, bool IS_G2>
__global__ __launch_bounds__(256, 2) void moe_gemm(
    const __half* __restrict__ Abase, const __half* __restrict__ Wh,
    const float* __restrict__ bias) {
    int e = blockIdx.z, nt = blockIdx.y, mt = blockIdx.x;
    int cnt = g_cnt[e];
    if (mt * 128 >= cnt) return;
    int rowbase = g_offs[e] + mt * 128;

    extern __shared__ float sm[];
    float* sgate = sm;                  // [128] gates (G2 only)
    char*  stage = (char*)(sm + 256);

    int t = threadIdx.x, lane = t & 31, wid = t >> 5;
    int wm = wid & 1, wn = wid >> 1;

    if (IS_G2 && t < 128) sgate[t] = g_rowgate[rowbase + t];

    // ---- producers: 4 x cp.async 16B per thread per chunk --------------
    int arow = t >> 1;                  // A m-row, 2 threads/row (32B each)
    const __half* pa;
    if (!IS_G2)
        pa = Abase + (size_t)g_rowtok[rowbase + arow] * KD + (t & 1) * 16;
    else
        pa = Abase + (size_t)(rowbase + arow) * KD + (t & 1) * 16;
    uint32_t aoff = (uint32_t)arow * (ROWH_A * 2) + (uint32_t)(t & 1) * 32;

    int brow = t >> 3;                  // B k-row, 8 threads/row (32B each)
    const __half* pb = Wh + ((size_t)e * KD + brow) * ND
                          + (size_t)nt * 128 + (t & 7) * 16;
    uint32_t boff = A_STAGE_B + (uint32_t)brow * (LDN_B * 2)
                  + (uint32_t)(t & 7) * 32;

    uint32_t sbst = smem_u32(stage);
    auto do_load = [&](int s) {
        uint32_t ab = sbst + (uint32_t)s * STAGE_B;
        cp16(ab + aoff,      pa);
        cp16(ab + aoff + 16, pa + 8);
        cp16(ab + boff,      pb);
        cp16(ab + boff + 16, pb + 8);
        pa += 32;
        pb += (size_t)32 * ND;
    };

    const int NCH = KD / 32;
    do_load(0); CP_COMMIT();
    do_load(1); CP_COMMIT();
    do_load(2); CP_COMMIT();

    // ldmatrix per-lane address components
    int rowA  = wm * 64 + ((lane >> 3) & 1) * 8 + (lane & 7);  // + mi*16
    int koffA = (lane >> 4) * 8;
    int kB    = lane & 7;                                       // + ks*16 (+8)
    int nB    = wn * 32 + (lane >> 3) * 8;

    float acc[4][4][4];
#pragma unroll
    for (int a = 0; a < 4; a++)
#pragma unroll
        for (int b = 0; b < 4; b++)
#pragma unroll
            for (int c = 0; c < 4; c++) acc[a][b][c] = 0.f;

#pragma unroll 1
    for (int c = 0; c < NCH; c++) {
        CP_WAIT2();
        __syncthreads();
        uint32_t As = sbst + (uint32_t)(c & 3) * STAGE_B;
        uint32_t Bs = As + A_STAGE_B;

#pragma unroll
        for (int ks = 0; ks < 2; ks++) {
            uint32_t af[4][4], b0[4], b1[4];
#pragma unroll
            for (int mi = 0; mi < 4; mi++)
                ldsm4(af[mi], As + (uint32_t)(rowA + mi * 16) * (ROWH_A * 2)
                                 + (uint32_t)(ks * 16 + koffA) * 2);
            ldsm4t(b0, Bs + (uint32_t)(ks * 16 + kB)     * (LDN_B * 2)
                          + (uint32_t)nB * 2);
            ldsm4t(b1, Bs + (uint32_t)(ks * 16 + 8 + kB) * (LDN_B * 2)
                          + (uint32_t)nB * 2);
#pragma unroll
            for (int mi = 0; mi < 4; mi++)
#pragma unroll
                for (int ni = 0; ni < 4; ni++)
                    mma16(acc[mi][ni], af[mi], b0[ni], b1[ni]);
        }
        if (c + 3 < NCH) do_load((c + 3) & 3);
        CP_COMMIT();
    }

    // ---------------------------- epilogue -----------------------------------
    const float* bp = bias + (size_t)e * ND + (size_t)nt * 128;
#pragma unroll
    for (int mi = 0; mi < 4; mi++) {
#pragma unroll
        for (int ni = 0; ni < 4; ni++) {
            int row = wm * 64 + mi * 16 + (lane >> 2);
            int col = wn * 32 + ni * 8 + 2 * (lane & 3);
            float2 bv = *(const float2*)(bp + col);
            if (!IS_G2) {
                __half2 h0 = __floats2half2_rn(
                    fmaxf(acc[mi][ni][0] + bv.x, 0.f),
                    fmaxf(acc[mi][ni][1] + bv.y, 0.f));
                __half2 h1 = __floats2half2_rn(
                    fmaxf(acc[mi][ni][2] + bv.x, 0.f),
                    fmaxf(acc[mi][ni][3] + bv.y, 0.f));
                *(__half2*)(g_Hh + (size_t)(rowbase + row) * D_HID +
                            (size_t)nt * 128 + col) = h0;
                *(__half2*)(g_Hh + (size_t)(rowbase + row + 8) * D_HID +
                            (size_t)nt * 128 + col) = h1;
            } else {
                float g0 = sgate[row], g1 = sgate[row + 8];
                float2 o0, o1;
                o0.x = (acc[mi][ni][0] + bv.x) * g0;
                o0.y = (acc[mi][ni][1] + bv.y) * g0;
                o1.x = (acc[mi][ni][2] + bv.x) * g1;
                o1.y = (acc[mi][ni][3] + bv.y) * g1;
                *(float2*)(g_Y + (size_t)(rowbase + row) * D_MODEL +
                           (size_t)nt * 128 + col) = o0;
                *(float2*)(g_Y + (size_t)(rowbase + row + 8) * D_MODEL +
                           (size_t)nt * 128 + col) = o1;
            }
        }
    }
}

// Combine: out[t] = Y[row0(t)] + Y[row1(t)]  (one block per token)
__global__ __launch_bounds__(256) void combine_kernel(float* __restrict__ out) {
    int t = blockIdx.x;
    int r0 = g_tokrow[t * 2 + 0];
    int r1 = g_tokrow[t * 2 + 1];
    int c = threadIdx.x * 4;
    float4 a = *(const float4*)(g_Y + (size_t)r0 * D_MODEL + c);
    float4 b = *(const float4*)(g_Y + (size_t)r1 * D_MODEL + c);
    float4 o;
    o.x = a.x + b.x; o.y = a.y + b.y; o.z = a.z + b.z; o.w = a.w + b.w;
    *(float4*)(out + (size_t)t * D_MODEL + c) = o;
}

// ============================================================================
extern "C" void kernel_launch(void* const* d_in, const int* in_sizes, int n_in,
                              void* d_out, int out_size) {
    const float* X  = (const float*)d_in[0];
    const float* Wr = (const float*)d_in[1];
    const float* br = (const float*)d_in[2];
    const float* W1 = (const float*)d_in[3];
    const float* b1 = (const float*)d_in[4];
    const float* W2 = (const float*)d_in[5];
    const float* b2 = (const float*)d_in[6];
    float* out = (float*)d_out;

    cudaFuncSetAttribute(moe_gemm<D_MODEL, D_HID, false>,
                         cudaFuncAttributeMaxDynamicSharedMemorySize, SMEM_BYTES);
    cudaFuncSetAttribute(moe_gemm<D_HID, D_MODEL, true>,
                         cudaFuncAttributeMaxDynamicSharedMemorySize, SMEM_BYTES);

    __half *xh_dev = nullptr, *hh_dev = nullptr, *w1h_dev = nullptr, *w2h_dev = nullptr;
    cudaGetSymbolAddress((void**)&xh_dev,  g_Xh);
    cudaGetSymbolAddress((void**)&hh_dev,  g_Hh);
    cudaGetSymbolAddress((void**)&w1h_dev, g_W1h);
    cudaGetSymbolAddress((void**)&w2h_dev, g_W2h);

    // (1) W convert + counter zero, (2) router, (3) dispatch, (4) gemm1 ...
    prep_kernel<<<(NBANKS * D_MODEL * D_HID) / (256 * 8), 256>>>(W1, W2);
    router_kernel<<<TOKENS / 8, 256>>>(X, Wr, br);
    dispatch_kernel<<<1, 256>>>();

    dim3 g1(32, D_HID / 128, NBANKS);     // mt_max x nt x expert
    moe_gemm<D_MODEL, D_HID, false><<<g1, 256, SMEM_BYTES>>>(xh_dev, w1h_dev, b1);
    dim3 g2(32, D_MODEL / 128, NBANKS);
    moe_gemm<D_HID, D_MODEL, true><<<g2, 256, SMEM_BYTES>>>(hh_dev, w2h_dev, b2);
    combine_kernel<<<TOKENS, 256>>>(out);
}